// round 11
// baseline (speedup 1.0000x reference)
#include <cuda_runtime.h>
#include <cuda_bf16.h>

// HungarianMatcher cost matrix:
//   C[bq, t] = -softmax(logits[bq])[label_t]
//            + 5*L1(pred_box[bq], tgt_box[t])            (cxcywh space)
//            - 2*GIoU(xyxy(pred_box[bq]), xyxy(tgt_box[t]))
//
// Inputs: d_in[0] pred_logits f32 [B,Q,C], d_in[1] pred_boxes f32 [B,Q,4],
//         d_in[2] tgt_labels i32 [T],      d_in[3] tgt_boxes  f32 [T,4]
// Output: f32 [B,Q,T]
//
// Structure: CTA owns RB=16 rows (softmax probs + box params in smem);
// each thread owns 4 adjacent targets, processed as TWO f32x2-packed pairs.
// The GIoU add/mul/fma tail runs on the packed fp32x2 pipe (FADD2/FMUL2/
// FFMA2); min/max/L1 stay scalar (no packed FMNMX on sm_103a). Results are
// stored packed via one st.global.cs.v2.b64 (128-bit) per (row, 4 targets).

#define BLOCK 256
#define RB    16
#define TB    4      // adjacent targets per thread
#define CPAD  96     // padded class stride (C <= 96)

using u64 = unsigned long long;

#define F2PACK(d, lo, hi)   asm("mov.b64 %0, {%1, %2};" : "=l"(d) : "f"(lo), "f"(hi))
#define F2UNPACK(lo, hi, s) asm("mov.b64 {%0, %1}, %2;" : "=f"(lo), "=f"(hi) : "l"(s))
#define F2ADD(d, a, b)      asm("add.rn.f32x2 %0, %1, %2;" : "=l"(d) : "l"(a), "l"(b))
#define F2MUL(d, a, b)      asm("mul.rn.f32x2 %0, %1, %2;" : "=l"(d) : "l"(a), "l"(b))
#define F2FMA(d, a, b, c)   asm("fma.rn.f32x2 %0, %1, %2, %3;" : "=l"(d) : "l"(a), "l"(b), "l"(c))
#define FRCP(d, a)          asm("rcp.approx.f32 %0, %1;" : "=f"(d) : "f"(a))

static __device__ __forceinline__ u64 k_neg1() { return 0xBF800000BF800000ULL; } // (-1,-1)
static __device__ __forceinline__ u64 k_neg2() { return 0xC0000000C0000000ULL; } // (-2,-2)

struct TgtState {
    float tcx, tcy, tw, th;     // cxcywh
    float tx1, ty1, tx2, ty2;   // xyxy
    int   lab;
};

__device__ __forceinline__ void make_tgt(TgtState& s, const float4 tb, const int lab,
                                         float& tarea)
{
    s.tcx = tb.x; s.tcy = tb.y; s.tw = tb.z; s.th = tb.w; s.lab = lab;
    s.tx1 = tb.x - 0.5f * tb.z;
    s.ty1 = tb.y - 0.5f * tb.w;
    s.tx2 = tb.x + 0.5f * tb.z;
    s.ty2 = tb.y + 0.5f * tb.w;
    tarea = (s.tx2 - s.tx1) * (s.ty2 - s.ty1);
}

// Packed cost for a pair of targets {sa, sb} against one row.
// A = px1 py1 px2 py2, Bv = pcx pcy pw ph. Returns (cost_a, cost_b) packed.
__device__ __forceinline__ u64 pair2_cost(
    const float4 A, const float4 Bv,
    const u64 pa2, const u64 pw2, const u64 ph2,
    const TgtState& sa, const TgtState& sb,
    const u64 tarea2, const u64 tw2, const u64 th2,
    const float clsa, const float clsb)
{
    const u64 NEG1 = k_neg1();
    const u64 NEG2 = k_neg2();

    // ---- scalar front: intersection (min/max) + L1 (abs) ----
    const float iwr0 = fminf(A.z, sa.tx2) - fmaxf(A.x, sa.tx1);
    const float ihr0 = fminf(A.w, sa.ty2) - fmaxf(A.y, sa.ty1);
    const float iwr1 = fminf(A.z, sb.tx2) - fmaxf(A.x, sb.tx1);
    const float ihr1 = fminf(A.w, sb.ty2) - fmaxf(A.y, sb.ty1);
    const float inter0 = fmaxf(iwr0, 0.0f) * fmaxf(ihr0, 0.0f);
    const float inter1 = fmaxf(iwr1, 0.0f) * fmaxf(ihr1, 0.0f);

    const float l10 = fabsf(Bv.x - sa.tcx) + fabsf(Bv.y - sa.tcy)
                    + fabsf(Bv.z - sa.tw)  + fabsf(Bv.w - sa.th);
    const float l11 = fabsf(Bv.x - sb.tcx) + fabsf(Bv.y - sb.tcy)
                    + fabsf(Bv.z - sb.tw)  + fabsf(Bv.w - sb.th);
    const float base0 = fmaf(5.0f, l10, -clsa);
    const float base1 = fmaf(5.0f, l11, -clsb);

    // ---- pack ----
    u64 iwr2, ihr2, int2, base2;
    F2PACK(iwr2, iwr0, iwr1);
    F2PACK(ihr2, ihr0, ihr1);
    F2PACK(int2, inter0, inter1);
    F2PACK(base2, base0, base1);

    // ---- packed GIoU tail ----
    u64 pt;   F2ADD(pt, pa2, tarea2);          // parea + tarea
    u64 uni;  F2FMA(uni, int2, NEG1, pt);      // pt - inter
    u64 pwtw; F2ADD(pwtw, pw2, tw2);           // pw + tw
    u64 ew;   F2FMA(ew, iwr2, NEG1, pwtw);     // (pw+tw) - iwr   (enclosing width)
    u64 phth; F2ADD(phth, ph2, th2);
    u64 eh;   F2FMA(eh, ihr2, NEG1, phth);
    u64 ea;   F2MUL(ea, ew, eh);               // enclosing area
    u64 tt;   F2FMA(tt, uni, NEG1, int2);      // inter - uni
    u64 mm;   F2MUL(mm, ea, tt);
    u64 num;  F2FMA(num, uni, uni, mm);        // uni^2 + ea*(inter-uni)
    u64 den;  F2MUL(den, uni, ea);

    float d0, d1; F2UNPACK(d0, d1, den);
    float r0, r1; FRCP(r0, d0); FRCP(r1, d1);  // matches __fdividef
    u64 rinv; F2PACK(rinv, r0, r1);
    u64 gt;   F2MUL(gt, num, rinv);            // gterm = iou - (ea-uni)/ea
    u64 cost; F2FMA(cost, gt, NEG2, base2);    // base - 2*gterm
    return cost;
}

__device__ __forceinline__ void do_row(
    const float* __restrict__ srp_r, const float* __restrict__ sprob_r,
    const TgtState& s0, const TgtState& s1, const TgtState& s2, const TgtState& s3,
    const u64 tareaP, const u64 twP, const u64 thP,
    const u64 tareaQ, const u64 twQ, const u64 thQ,
    float4* optr)
{
    const float4 A  = *reinterpret_cast<const float4*>(srp_r);      // px1 py1 px2 py2
    const float4 Bv = *reinterpret_cast<const float4*>(srp_r + 4);  // pcx pcy pw  ph
    const float parea = srp_r[8];

    u64 pw2, ph2, pa2;
    F2PACK(pw2, Bv.z, Bv.z);
    F2PACK(ph2, Bv.w, Bv.w);
    F2PACK(pa2, parea, parea);

    const float c0 = sprob_r[s0.lab];
    const float c1 = sprob_r[s1.lab];
    const float c2 = sprob_r[s2.lab];
    const float c3 = sprob_r[s3.lab];

    const u64 cP = pair2_cost(A, Bv, pa2, pw2, ph2, s0, s1, tareaP, twP, thP, c0, c1);
    const u64 cQ = pair2_cost(A, Bv, pa2, pw2, ph2, s2, s3, tareaQ, twQ, thQ, c2, c3);

    asm volatile("st.global.cs.v2.b64 [%0], {%1, %2};"
                 :: "l"(optr), "l"(cP), "l"(cQ) : "memory");
}

template<int TCONST>
__global__ __launch_bounds__(BLOCK)
void matcher_rt4p_kernel(const float* __restrict__ logits,
                         const float* __restrict__ boxes,
                         const int*   __restrict__ labels,
                         const float* __restrict__ tboxes,
                         float*       __restrict__ out,
                         int BQ, int C, int T_rt)
{
    const int T = TCONST ? TCONST : T_rt;

    __shared__ float sprob[RB][CPAD];  // softmax probs per row
    __shared__ float srp[RB][12];      // px1,py1,px2,py2, pcx,pcy,pw,ph, parea, pad

    const int tid = threadIdx.x;
    const int wid = tid >> 5;
    const int lid = tid & 31;
    const int row0 = blockIdx.y * RB;

    // ---- setup: 8 warps, each does softmax + box params for 2 rows ----
    for (int rr = wid; rr < RB; rr += (BLOCK / 32)) {
        const int row = row0 + rr;
        if (row < BQ) {
            const float* lrow = logits + (size_t)row * C;
            float v0 = (lid      < C) ? lrow[lid]      : -3.0e38f;
            float v1 = (lid + 32 < C) ? lrow[lid + 32] : -3.0e38f;
            float v2 = (lid + 64 < C) ? lrow[lid + 64] : -3.0e38f;
            float m = fmaxf(fmaxf(v0, v1), v2);
            #pragma unroll
            for (int o = 16; o; o >>= 1) m = fmaxf(m, __shfl_xor_sync(0xffffffffu, m, o));
            float e0 = __expf(v0 - m), e1 = __expf(v1 - m), e2 = __expf(v2 - m);
            float s = e0 + e1 + e2;
            #pragma unroll
            for (int o = 16; o; o >>= 1) s += __shfl_xor_sync(0xffffffffu, s, o);
            const float rinv = __fdividef(1.0f, s);
            if (lid      < C) sprob[rr][lid]      = e0 * rinv;
            if (lid + 32 < C) sprob[rr][lid + 32] = e1 * rinv;
            if (lid + 64 < C) sprob[rr][lid + 64] = e2 * rinv;
            if (lid == 0) {
                const float4 pb = reinterpret_cast<const float4*>(boxes)[row];
                const float px1 = pb.x - 0.5f * pb.z;
                const float py1 = pb.y - 0.5f * pb.w;
                const float px2 = pb.x + 0.5f * pb.z;
                const float py2 = pb.y + 0.5f * pb.w;
                srp[rr][0] = px1;  srp[rr][1] = py1;
                srp[rr][2] = px2;  srp[rr][3] = py2;
                srp[rr][4] = pb.x; srp[rr][5] = pb.y;
                srp[rr][6] = pb.z; srp[rr][7] = pb.w;
                srp[rr][8] = (px2 - px1) * (py2 - py1);
            }
        }
    }
    __syncthreads();

    const int rmax = min(RB, BQ - row0);
    const int nchunks = T / (BLOCK * TB);   // launcher guarantees divisibility

    for (int c = 0; c < nchunks; c++) {
        const int t0 = c * (BLOCK * TB) + tid * TB;

        const int4 lab4 = *reinterpret_cast<const int4*>(labels + t0);
        const float4* tbp = reinterpret_cast<const float4*>(tboxes) + t0;
        TgtState s0, s1, s2, s3;
        float ta0, ta1, ta2, ta3;
        make_tgt(s0, tbp[0], lab4.x, ta0);
        make_tgt(s1, tbp[1], lab4.y, ta1);
        make_tgt(s2, tbp[2], lab4.z, ta2);
        make_tgt(s3, tbp[3], lab4.w, ta3);

        u64 tareaP, twP, thP, tareaQ, twQ, thQ;
        F2PACK(tareaP, ta0, ta1);
        F2PACK(twP, s0.tw, s1.tw);
        F2PACK(thP, s0.th, s1.th);
        F2PACK(tareaQ, ta2, ta3);
        F2PACK(twQ, s2.tw, s3.tw);
        F2PACK(thQ, s2.th, s3.th);

        float4* obase = reinterpret_cast<float4*>(out + (size_t)row0 * T + t0);
        const int ostride = T >> 2;   // compile-time for TCONST -> immediate offsets

        if (rmax == RB) {
            #pragma unroll
            for (int r = 0; r < RB; r++)
                do_row(&srp[r][0], &sprob[r][0], s0, s1, s2, s3,
                       tareaP, twP, thP, tareaQ, twQ, thQ, obase + r * ostride);
        } else {
            for (int r = 0; r < rmax; r++)
                do_row(&srp[r][0], &sprob[r][0], s0, s1, s2, s3,
                       tareaP, twP, thP, tareaQ, twQ, thQ, obase + r * ostride);
        }
    }
}

// ---- generic fallback (C > 96 or T not divisible): row-per-CTA kernel ----
__global__ __launch_bounds__(BLOCK)
void matcher_fallback_kernel(const float* __restrict__ logits,
                             const float* __restrict__ boxes,
                             const int*   __restrict__ labels,
                             const float* __restrict__ tboxes,
                             float*       __restrict__ out,
                             int C, int T)
{
    __shared__ float prob[1024];
    __shared__ float red[BLOCK / 32];

    const int row = blockIdx.x;
    const int tid = threadIdx.x;
    const int wid = tid >> 5;
    const int lid = tid & 31;

    float m = -3.0e38f;
    for (int c = tid; c < C; c += BLOCK) m = fmaxf(m, logits[(size_t)row * C + c]);
    #pragma unroll
    for (int o = 16; o; o >>= 1) m = fmaxf(m, __shfl_xor_sync(0xffffffffu, m, o));
    if (lid == 0) red[wid] = m;
    __syncthreads();
    float bm = red[0];
    #pragma unroll
    for (int i = 1; i < BLOCK / 32; i++) bm = fmaxf(bm, red[i]);
    __syncthreads();

    float s = 0.0f;
    for (int c = tid; c < C; c += BLOCK) {
        float e = __expf(logits[(size_t)row * C + c] - bm);
        prob[c] = e;
        s += e;
    }
    #pragma unroll
    for (int o = 16; o; o >>= 1) s += __shfl_xor_sync(0xffffffffu, s, o);
    if (lid == 0) red[wid] = s;
    __syncthreads();
    float bs = red[0];
    #pragma unroll
    for (int i = 1; i < BLOCK / 32; i++) bs += red[i];
    float rinv = __fdividef(1.0f, bs);
    __syncthreads();
    for (int c = tid; c < C; c += BLOCK) prob[c] *= rinv;
    __syncthreads();

    const float4 pb = reinterpret_cast<const float4*>(boxes)[row];
    const float px1 = pb.x - 0.5f * pb.z, py1 = pb.y - 0.5f * pb.w;
    const float px2 = pb.x + 0.5f * pb.z, py2 = pb.y + 0.5f * pb.w;
    const float parea = (px2 - px1) * (py2 - py1);
    float* orow = out + (size_t)row * T;

    for (int t = tid; t < T; t += BLOCK) {
        const float4 tb = reinterpret_cast<const float4*>(tboxes)[t];
        const float cls = prob[labels[t]];
        const float l1 = fabsf(pb.x - tb.x) + fabsf(pb.y - tb.y)
                       + fabsf(pb.z - tb.z) + fabsf(pb.w - tb.w);
        const float tx1 = tb.x - 0.5f * tb.z, ty1 = tb.y - 0.5f * tb.w;
        const float tx2 = tb.x + 0.5f * tb.z, ty2 = tb.y + 0.5f * tb.w;
        const float tarea = (tx2 - tx1) * (ty2 - ty1);
        const float iwr = fminf(px2, tx2) - fmaxf(px1, tx1);
        const float ihr = fminf(py2, ty2) - fmaxf(py1, ty1);
        const float inter = fmaxf(iwr, 0.0f) * fmaxf(ihr, 0.0f);
        const float uni = parea + tarea - inter;
        const float ew = (pb.z + tb.z) - iwr;
        const float eh = (pb.w + tb.w) - ihr;
        const float earea = ew * eh;
        const float num   = fmaf(uni, uni, earea * (inter - uni));
        const float gterm = __fdividef(num, uni * earea);
        float cost = fmaf(5.0f, l1, -cls);
        cost = fmaf(-2.0f, gterm, cost);
        __stcs(orow + t, cost);
    }
}

extern "C" void kernel_launch(void* const* d_in, const int* in_sizes, int n_in,
                              void* d_out, int out_size)
{
    const float* logits = (const float*)d_in[0];
    const float* boxes  = (const float*)d_in[1];
    const int*   labels = (const int*)  d_in[2];
    const float* tboxes = (const float*)d_in[3];
    float* out = (float*)d_out;

    const int BQ = in_sizes[1] / 4;          // pred_boxes is [BQ, 4]
    const int C  = in_sizes[0] / BQ;         // logits [BQ, C]
    const int T  = in_sizes[2];              // labels [T]

    if (C <= CPAD && (T % (BLOCK * TB)) == 0) {
        dim3 grid(1, (BQ + RB - 1) / RB);
        if (T == 2048)
            matcher_rt4p_kernel<2048><<<grid, BLOCK>>>(logits, boxes, labels, tboxes, out, BQ, C, T);
        else
            matcher_rt4p_kernel<0><<<grid, BLOCK>>>(logits, boxes, labels, tboxes, out, BQ, C, T);
    } else {
        matcher_fallback_kernel<<<BQ, BLOCK>>>(logits, boxes, labels, tboxes, out, C, T);
    }
}